// round 1
// baseline (speedup 1.0000x reference)
#include <cuda_runtime.h>
#include <math.h>

#define DEV_INLINE __device__ __forceinline__

constexpr int B_   = 32;
constexpr int H_   = 32;
constexpr int HKV_ = 8;
constexpr int D_   = 128;
constexpr int G_   = 4;      // H_/HKV_
constexpr int N_   = 4096;
constexpr int NB_  = 256;    // blocks per sequence
constexpr int SPLIT = 4;     // token splits per (b,kh)
constexpr int WARPS = 8;     // warps per CTA in main kernel
constexpr int TPS = N_ / SPLIT;   // 1024 tokens per split
constexpr int TPW = TPS / WARPS;  // 128 tokens per warp
constexpr float SCALE_ = 0.08838834764831845f;

// Partial results scratch (allocation-free: __device__ globals)
// layout: [b][kh][split][g] -> acc[128], (M,L)
__device__ float g_pacc[(size_t)B_ * HKV_ * SPLIT * G_ * D_];
__device__ float g_pml[(size_t)B_ * HKV_ * SPLIT * G_ * 2];

DEV_INLINE float4 ldg4(const float* p) {
    return __ldg(reinterpret_cast<const float4*>(p));
}

DEV_INLINE void token_step(const float* kp, const float* vp, const float qr[16],
                           float& m, float& l, float acc[16])
{
    // K row segment for this lane (16 floats)
    float4 k0 = ldg4(kp +  0);
    float4 k1 = ldg4(kp +  4);
    float4 k2 = ldg4(kp +  8);
    float4 k3 = ldg4(kp + 12);
    // V row segment (issue early for MLP)
    float4 v0 = ldg4(vp +  0);
    float4 v1 = ldg4(vp +  4);
    float4 v2 = ldg4(vp +  8);
    float4 v3 = ldg4(vp + 12);

    float s = qr[0]*k0.x + qr[1]*k0.y + qr[2]*k0.z + qr[3]*k0.w;
    s += qr[4]*k1.x + qr[5]*k1.y + qr[6]*k1.z + qr[7]*k1.w;
    s += qr[8]*k2.x + qr[9]*k2.y + qr[10]*k2.z + qr[11]*k2.w;
    s += qr[12]*k3.x + qr[13]*k3.y + qr[14]*k3.z + qr[15]*k3.w;

    // reduce over the 8 lanes of this g-group
    s += __shfl_xor_sync(0xffffffffu, s, 1);
    s += __shfl_xor_sync(0xffffffffu, s, 2);
    s += __shfl_xor_sync(0xffffffffu, s, 4);

    if (s > m) {   // rare path (max update): rescale
        float c = __expf(m - s);
        l *= c;
        #pragma unroll
        for (int k = 0; k < 16; k++) acc[k] *= c;
        m = s;
    }
    float p = __expf(s - m);
    l += p;

    acc[0]  += p * v0.x;  acc[1]  += p * v0.y;  acc[2]  += p * v0.z;  acc[3]  += p * v0.w;
    acc[4]  += p * v1.x;  acc[5]  += p * v1.y;  acc[6]  += p * v1.z;  acc[7]  += p * v1.w;
    acc[8]  += p * v2.x;  acc[9]  += p * v2.y;  acc[10] += p * v2.z;  acc[11] += p * v2.w;
    acc[12] += p * v3.x;  acc[13] += p * v3.y;  acc[14] += p * v3.z;  acc[15] += p * v3.w;
}

__global__ __launch_bounds__(256, 2)
void attn_main(const float* __restrict__ Q,
               const float* __restrict__ Kc,
               const float* __restrict__ Vc,
               const float* __restrict__ cosp,
               const float* __restrict__ sinp,
               const int* __restrict__ bt)
{
    const int b  = blockIdx.z;
    const int kh = blockIdx.y;
    const int sp = blockIdx.x;
    const int tid = threadIdx.x;
    const int w   = tid >> 5;
    const int lid = tid & 31;
    const int g   = lid >> 3;       // query-head group 0..3
    const int seg = lid & 7;        // d-segment 0..7
    const int d0  = seg * 16;
    const int h   = g * HKV_ + kh;  // query head

    // Load RoPE'd Q segment (pre-scaled)
    float qr[16];
    {
        const float* qb = Q + ((size_t)b * H_ + h) * D_;
        const float* cb = cosp + (size_t)b * D_;
        const float* sb = sinp + (size_t)b * D_;
        const float sign = (d0 < 64) ? -1.f : 1.f;
        const int dp = d0 ^ 64;
        #pragma unroll
        for (int k = 0; k < 16; k++) {
            qr[k] = (qb[d0 + k] * cb[d0 + k] + sign * qb[dp + k] * sb[d0 + k]) * SCALE_;
        }
    }

    float m = -1e30f, l = 0.f;
    float acc[16];
    #pragma unroll
    for (int k = 0; k < 16; k++) acc[k] = 0.f;

    const int t0 = sp * TPS + w * TPW;
    const int t1 = min(t0 + TPW, N_ - 1);   // exclude current token (handled in combine)
    const int* btb = bt + (size_t)b * NB_;

    for (int t = t0; t < t1; t += 16) {
        const int blk = __ldg(btb + (t >> 4));
        const float* kb = Kc + (size_t)blk * 16384 + kh * 2048 + d0;
        const float* vb = Vc + (size_t)blk * 16384 + kh * 2048 + d0;
        const int jm = min(16, t1 - t);
        if (jm == 16) {
            #pragma unroll 4
            for (int j = 0; j < 16; j++)
                token_step(kb + j * 128, vb + j * 128, qr, m, l, acc);
        } else {
            for (int j = 0; j < jm; j++)
                token_step(kb + j * 128, vb + j * 128, qr, m, l, acc);
        }
    }

    // CTA-level combine of the 8 warp partials
    __shared__ float s_acc[WARPS][G_][D_];   // 16 KB
    __shared__ float s_m[WARPS][G_];
    __shared__ float s_l[WARPS][G_];

    #pragma unroll
    for (int k = 0; k < 16; k++) s_acc[w][g][d0 + k] = acc[k];
    if (seg == 0) { s_m[w][g] = m; s_l[w][g] = l; }
    __syncthreads();

    for (int idx = tid; idx < G_ * D_; idx += 256) {
        const int gg = idx >> 7;
        const int d  = idx & 127;
        float M = -1e30f;
        #pragma unroll
        for (int ww = 0; ww < WARPS; ww++) M = fmaxf(M, s_m[ww][gg]);
        float A = 0.f, L = 0.f;
        #pragma unroll
        for (int ww = 0; ww < WARPS; ww++) {
            float c = __expf(s_m[ww][gg] - M);
            A += s_acc[ww][gg][d] * c;
            L += s_l[ww][gg] * c;
        }
        const size_t o = (((size_t)b * HKV_ + kh) * SPLIT + sp) * G_ + gg;
        g_pacc[o * D_ + d] = A;
        if (d == 0) { g_pml[o * 2] = M; g_pml[o * 2 + 1] = L; }
    }
}

__global__ __launch_bounds__(128)
void attn_combine(const float* __restrict__ Q,
                  const float* __restrict__ K,
                  const float* __restrict__ V,
                  const float* __restrict__ cosp,
                  const float* __restrict__ sinp,
                  float* __restrict__ out)
{
    const int h = blockIdx.x;
    const int b = blockIdx.y;
    const int g  = h >> 3;
    const int kh = h & 7;
    const int d    = threadIdx.x;     // 0..127
    const int lane = d & 31;
    const int wrp  = d >> 5;

    const float cv = cosp[(size_t)b * D_ + d];
    const float sv = sinp[(size_t)b * D_ + d];
    const float sign = (d < 64) ? -1.f : 1.f;
    const float* qb = Q + ((size_t)b * H_ + h) * D_;
    const float* kb = K + ((size_t)b * HKV_ + kh) * D_;
    const float qrv = qb[d] * cv + sign * qb[d ^ 64] * sv;
    const float krv = kb[d] * cv + sign * kb[d ^ 64] * sv;

    // block reduce qr·kr over 128 threads
    __shared__ float red[4];
    float part = qrv * krv;
    #pragma unroll
    for (int o = 16; o; o >>= 1) part += __shfl_xor_sync(0xffffffffu, part, o);
    if (lane == 0) red[wrp] = part;
    __syncthreads();
    const float s_cur = (red[0] + red[1] + red[2] + red[3]) * SCALE_;

    const size_t base = ((size_t)b * HKV_ + kh) * SPLIT * G_ + g;
    float M = s_cur;
    #pragma unroll
    for (int i = 0; i < SPLIT; i++)
        M = fmaxf(M, g_pml[(base + (size_t)i * G_) * 2]);

    float ec = __expf(s_cur - M);
    float L  = ec;
    float o_ = ec * V[((size_t)b * HKV_ + kh) * D_ + d];   // current token: raw V
    #pragma unroll
    for (int i = 0; i < SPLIT; i++) {
        const size_t pi = base + (size_t)i * G_;
        const float c = __expf(g_pml[pi * 2] - M);
        L  += g_pml[pi * 2 + 1] * c;
        o_ += g_pacc[pi * D_ + d] * c;
    }
    out[((size_t)b * H_ + h) * D_ + d] = o_ / L;
}

extern "C" void kernel_launch(void* const* d_in, const int* in_sizes, int n_in,
                              void* d_out, int out_size)
{
    const float* Q    = (const float*)d_in[0];
    const float* K    = (const float*)d_in[1];
    const float* V    = (const float*)d_in[2];
    const float* Kc   = (const float*)d_in[3];
    const float* Vc   = (const float*)d_in[4];
    const float* cosp = (const float*)d_in[5];
    const float* sinp = (const float*)d_in[6];
    const int*   bt   = (const int*)d_in[7];
    // d_in[8] = save_slots (unused in decode ref), d_in[9] = input_length (fixed 4096)
    float* out = (float*)d_out;

    dim3 grid_main(SPLIT, HKV_, B_);
    attn_main<<<grid_main, 256>>>(Q, Kc, Vc, cosp, sinp, bt);

    dim3 grid_comb(H_, B_);
    attn_combine<<<grid_comb, 128>>>(Q, K, V, cosp, sinp, out);
}